// round 16
// baseline (speedup 1.0000x reference)
#include <cuda_runtime.h>
#include <cuda_fp16.h>

#define NB 16
#define NH 512
#define NW 512
#define NPIX (NB*NH*NW)
#define NIT 128

// ---------------- device scratch (allocation-free), 16B-aligned ----------------
__device__ __align__(16) __half2 g_xbar[NPIX];  // fp16 transient: extrapolated primal (TV path only)
__device__ __align__(16) float2  g_P1[NPIX];    // dual p1 (fp32), S-conjugated, [b][pw][ph] digit-reversed
__device__ __align__(16) __half2 g_p2a[NPIX];   // fp16 TV dual, h-component (clamp re-anchors each iter)
__device__ __align__(16) __half2 g_p2b[NPIX];   // fp16 TV dual, w-component
__device__ __align__(16) __half2 g_u1[NPIX];    // fp16 transient: rowFFT(S*xbar), [b][h][pw]
__device__ __align__(16) __half2 g_T[NPIX];     // fp16 transient: col-iFFT(m*P1), [b][h][pw]
__device__ __align__(16) __half2 g_Y[NPIX];     // fp16: S*y, permuted to [b][pw][ph]
__device__ __align__(16) __half  g_lamh[NPIX];  // fp16 lambda
__device__ __align__(16) float   g_M[NH*NW];    // mask permuted to [pw][ph]
__device__ __align__(16) float2  g_tw[512];     // exp(-2*pi*i*j/512)

#define SIG    ((float)(0.97/3.0))
#define TAU    ((float)(0.97/3.0))
#define INV1PS ((float)(1.0/(1.0+0.97/3.0)))
#define SCL    (0.044194173824159223f)   // 1/sqrt(512)

// ---------------- complex helpers ----------------
__device__ __forceinline__ float2 cadd(float2 a, float2 b){ return make_float2(a.x+b.x, a.y+b.y); }
__device__ __forceinline__ float2 csub(float2 a, float2 b){ return make_float2(a.x-b.x, a.y-b.y); }
__device__ __forceinline__ float2 cmul(float2 a, float2 b){ return make_float2(a.x*b.x - a.y*b.y, a.x*b.y + a.y*b.x); }
__device__ __forceinline__ float2 cmulc(float2 a, float2 b){ return make_float2(a.x*b.x + a.y*b.y, a.y*b.x - a.x*b.y); } // a*conj(b)

template<int S>
__device__ __forceinline__ float2 rot90(float2 z){   // multiply by S*i
    return (S < 0) ? make_float2(z.y, -z.x) : make_float2(-z.y, z.x);
}

// 8-point DFT: X[k] = sum_n x[n] exp(S*2*pi*i*n*k/8), regs in place
template<int S>
__device__ __forceinline__ void dft8(float2 v[8]){
    const float sf = (float)S;
    float2 a0 = cadd(v[0], v[4]), a1 = csub(v[0], v[4]);
    float2 a2 = cadd(v[2], v[6]), a3 = csub(v[2], v[6]);
    float2 a4 = cadd(v[1], v[5]), a5 = csub(v[1], v[5]);
    float2 a6 = cadd(v[3], v[7]), a7 = csub(v[3], v[7]);
    float2 w3 = rot90<S>(a3);
    float2 w7 = rot90<S>(a7);
    float2 E0 = cadd(a0, a2), E2 = csub(a0, a2);
    float2 E1 = cadd(a1, w3), E3 = csub(a1, w3);
    float2 O0 = cadd(a4, a6), O2 = csub(a4, a6);
    float2 O1 = cadd(a5, w7), O3 = csub(a5, w7);
    const float r = 0.7071067811865476f;
    float2 t1 = make_float2(r*(O1.x - sf*O1.y), r*(O1.y + sf*O1.x));
    float2 t2 = rot90<S>(O2);
    float2 t3 = make_float2(r*(-O3.x - sf*O3.y), r*(-O3.y + sf*O3.x));
    v[0]=cadd(E0,O0); v[4]=csub(E0,O0);
    v[1]=cadd(E1,t1); v[5]=csub(E1,t1);
    v[2]=cadd(E2,t2); v[6]=csub(E2,t2);
    v[3]=cadd(E3,t3); v[7]=csub(E3,t3);
}

// exchange mappings (conflict-free for their access patterns)
__device__ __forceinline__ int xA(int i){ return i + ((i >> 6) << 3); }  // 64-block exchanges: +8 pad per 64
__device__ __forceinline__ int xB(int i){ return i + (i >> 3); }         // 8-block exchanges:  +1 pad per 8
#define EXSZ 576

// 512-pt FFT, 64 threads (t=0..63), 8 complex regs/thread. Unscaled.
// xA exchange is 64-thread-wide -> __syncthreads(); xB exchange couples only the
// 8 consecutive lanes sharing k0 -> __syncwarp(); INV's opening xB write is each
// thread's own strip -> no sync crossing calls.
template<bool FWD>
__device__ __forceinline__ void fft512_line(float2 r[8], int t, float2* ex){
    int k0 = t >> 3, m2 = t & 7;
    if (FWD){
        dft8<-1>(r);
        #pragma unroll
        for (int k = 1; k < 8; k++) r[k] = cmul(r[k], g_tw[t*k]);
        __syncthreads();
        #pragma unroll
        for (int k = 0; k < 8; k++) ex[xA((k<<6) + t)] = r[k];
        __syncthreads();
        #pragma unroll
        for (int m1 = 0; m1 < 8; m1++) r[m1] = ex[xA((k0<<6) + m2 + (m1<<3))];
        dft8<-1>(r);
        #pragma unroll
        for (int j = 1; j < 8; j++) r[j] = cmul(r[j], g_tw[(m2<<3)*j]);
        __syncwarp();
        #pragma unroll
        for (int j = 0; j < 8; j++) ex[xB((k0<<6) + (j<<3) + m2)] = r[j];
        __syncwarp();
        #pragma unroll
        for (int j = 0; j < 8; j++) r[j] = ex[xB((t<<3) + j)];
        dft8<-1>(r);
    } else {
        dft8<1>(r);
        #pragma unroll
        for (int m = 0; m < 8; m++) ex[xB((t<<3) + m)] = r[m];   // own strip, no pre-sync
        __syncwarp();
        #pragma unroll
        for (int j = 0; j < 8; j++) r[j] = ex[xB((k0<<6) + (j<<3) + m2)];
        #pragma unroll
        for (int j = 1; j < 8; j++) r[j] = cmulc(r[j], g_tw[(m2<<3)*j]);
        dft8<1>(r);
        __syncwarp();                                             // xB reads done before xA writes
        #pragma unroll
        for (int m1 = 0; m1 < 8; m1++) ex[xA((k0<<6) + m2 + (m1<<3))] = r[m1];
        __syncthreads();
        #pragma unroll
        for (int k = 0; k < 8; k++) r[k] = ex[xA((k<<6) + t)];
        #pragma unroll
        for (int k = 1; k < 8; k++) r[k] = cmulc(r[k], g_tw[t*k]);
        dft8<1>(r);
    }
}

__device__ __forceinline__ int rev8(int p){ return ((p & 7) << 6) | (p & 56) | (p >> 6); }

// ---------------- init kernels ----------------
__global__ void k_tw(){
    int j = threadIdx.x;
    double a = -6.283185307179586476925286766559 * (double)j / 512.0;
    g_tw[j] = make_float2((float)cos(a), (float)sin(a));
}

__global__ void k_init(const float* __restrict__ ir, const float* __restrict__ ii,
                       const float* __restrict__ kr, const float* __restrict__ ki,
                       const float* __restrict__ lam,
                       const int* __restrict__ mask, float2* __restrict__ xout){
    int i = blockIdx.x*256 + threadIdx.x;
    float2 x0 = make_float2(ir[i], ii[i]);
    xout[i] = x0;
    g_xbar[i] = __floats2half2_rn(x0.x, x0.y);
    __half2 hz = __floats2half2_rn(0.f, 0.f);
    g_P1[i] = make_float2(0.f, 0.f);
    g_p2a[i] = hz; g_p2b[i] = hz;
    g_lamh[i] = __float2half(lam[i]);
    // Y transposed+permuted: i = (b*512 + pw)*512 + ph
    int b = i >> 18, pw = (i >> 9) & 511, ph = i & 511;
    int kh = rev8(ph), kw = rev8(pw);
    float sg = ((kh + kw) & 1) ? -1.f : 1.f;
    int src = (b << 18) | (kh << 9) | kw;
    g_Y[i] = __floats2half2_rn(sg*kr[src], sg*ki[src]);
    if (i < NH*NW){
        int pw2 = i >> 9, ph2 = i & 511;
        g_M[i] = (float)mask[(rev8(ph2) << 9) | rev8(pw2)];
    }
}

// ---------------- bootstrap: U1 = rowFFT(S*xbar), fp16 in/out ----------------
__global__ __launch_bounds__(256) void k_rowF(){
    __shared__ float2 sh_ex[4*EXSZ];
    int tid = threadIdx.x;
    int grp = tid >> 6, t = tid & 63;
    int row = blockIdx.x*4 + grp;         // row = b*512 + h
    int h = row & 511;
    float2* ex = sh_ex + grp*EXSZ;
    float sgn = ((h + t) & 1) ? -1.f : 1.f;
    float2 r[8];
    const __half2* src = g_xbar + ((long)row << 9);
    #pragma unroll
    for (int a = 0; a < 8; a++){
        float2 v = __half22float2(src[t + (a<<6)]);
        r[a] = make_float2(sgn*v.x, sgn*v.y);
    }
    fft512_line<true>(r, t, ex);
    uint4 stg[2];
    __half2* sp = (__half2*)stg;
    #pragma unroll
    for (int j = 0; j < 8; j++) sp[j] = __floats2half2_rn(r[j].x*SCL, r[j].y*SCL);
    uint4* dst = (uint4*)(g_u1 + ((long)row << 9) + (t<<3));
    dst[0] = stg[0]; dst[1] = stg[1];
}

// ---------------- fused kernel: col-role (FFT) + p2-role (TV prox), grid-concatenated ----------------
// 128-thread blocks: reg cap stays 64 (65536/1024), barriers couple 4 warps, 8 contexts/SM.
#define CTILE 2
#define CPITCH 3
#define COLSMEM (2*EXSZ*sizeof(float2))       // 9216 B; half2 tile (512*3*4=6144 B) overlays exchange
#define COLBLKS (NB*256)                      // 4096  (2 columns per block)
#define P2BLKS  (NPIX/512)                    // 8192  (one image row per block: 128 thr x 4 px)
#define FUSEGRID (COLBLKS + P2BLKS)           // 12288, interleave 1:2 (bid%3)

__device__ __forceinline__ void col_role(int cb, char* smraw){
    __half2* tile = (__half2*)smraw;           // 512 x CPITCH half2 (6144 B)
    float2*  exb  = (float2*)smraw;            // overlays tile
    int tid = threadIdx.x;
    int b  = cb >> 8;
    int w0 = (cb & 255) * CTILE;
    int g  = tid >> 6, t = tid & 63;
    float2* ex = exb + g*EXSZ;

    // load U1 tile: thread tid loads rows tid, +128, +256, +384 (CTILE half2 = 8B = 1 uint2)
    #pragma unroll
    for (int rr = 0; rr < 4; rr++){
        int hh = tid + (rr<<7);
        uint2 v = *(const uint2*)(g_u1 + (((long)(b<<9) + hh) << 9) + w0);
        const __half2* hv = (const __half2*)&v;
        __half2* dst = tile + hh*CPITCH;
        dst[0] = hv[0]; dst[1] = hv[1];
    }
    __syncthreads();

    // gather column pw = w0+g into regs (reg a = element h = t+64a); stride 3 coprime 32 -> conflict-free
    float2 r[8];
    #pragma unroll
    for (int a = 0; a < 8; a++) r[a] = __half22float2(tile[(t + (a<<6))*CPITCH + g]);
    // tile dead; FWD fft's pre-write __syncthreads fences the aliased exchange writes

    fft512_line<true>(r, t, ex);   // reg j = u at ph = 8t+j (unscaled)

    // pointwise: P1 prox + mask — short live ranges; Y fp16
    {
        int pw = w0 + g;
        long base = (((long)(b<<9) + pw) << 9) + (t<<3);
        const float4* p1p = (const float4*)(g_P1 + base);
        const uint4*  yp  = (const uint4*)(g_Y  + base);   // 8 half2 = 2 uint4
        const float4* mp  = (const float4*)(g_M + ((long)pw << 9) + (t<<3));
        float4* p1o = (float4*)(g_P1 + base);
        uint4 yv[2] = {yp[0], yp[1]};
        const __half2* yh = (const __half2*)yv;
        float4 mv0 = mp[0], mv1 = mp[1];
        const float* m8a = (const float*)&mv0;
        const float* m8b = (const float*)&mv1;
        #pragma unroll
        for (int q = 0; q < 4; q++){
            float4 p1v = p1p[q];
            float m0 = (q < 2) ? m8a[2*q]   : m8b[2*q-4];
            float m1 = (q < 2) ? m8a[2*q+1] : m8b[2*q-3];
            int j = 2*q;
            float2 yy0 = __half22float2(yh[j]);
            float2 yy1 = __half22float2(yh[j+1]);
            float nx0 = (p1v.x + SIG*(m0*(r[j].x*SCL))   - SIG*yy0.x) * INV1PS;
            float ny0 = (p1v.y + SIG*(m0*(r[j].y*SCL))   - SIG*yy0.y) * INV1PS;
            float nx1 = (p1v.z + SIG*(m1*(r[j+1].x*SCL)) - SIG*yy1.x) * INV1PS;
            float ny1 = (p1v.w + SIG*(m1*(r[j+1].y*SCL)) - SIG*yy1.y) * INV1PS;
            p1o[q] = make_float4(nx0, ny0, nx1, ny1);
            r[j]   = make_float2(m0*nx0, m0*ny0);
            r[j+1] = make_float2(m1*nx1, m1*ny1);
        }
    }

    fft512_line<false>(r, t, ex);  // reg a = element h = t+64a (unscaled)

    __syncthreads();               // all exchange reads done before tile re-staging (overlay)
    #pragma unroll
    for (int a = 0; a < 8; a++)
        tile[(t + (a<<6))*CPITCH + g] = __floats2half2_rn(r[a].x*SCL, r[a].y*SCL);
    __syncthreads();
    #pragma unroll
    for (int rr = 0; rr < 4; rr++){
        int hh = tid + (rr<<7);
        const __half2* s2 = tile + hh*CPITCH;
        uint2 v;
        __half2* hv = (__half2*)&v;
        hv[0] = s2[0]; hv[1] = s2[1];
        *(uint2*)(g_T + (((long)(b<<9) + hh) << 9) + w0) = v;
    }
}

// p2-role: one image row per block; 4 consecutive px/thread, uint4-vectorized
__device__ __forceinline__ void p2_role4(int pid){
    int tid = threadIdx.x;
    long i0 = (long)pid*512 + tid*4;
    int w = tid*4;
    int h = (int)((i0 >> 9) & 511);
    long ih = (i0 & ~((long)511<<9)) | ((long)((h+1)&511)<<9);   // same b,w; row h+1
    uint4 xbv = *(const uint4*)(g_xbar + i0);
    uint4 xhv = *(const uint4*)(g_xbar + ih);
    uint4 pav = *(const uint4*)(g_p2a + i0);
    uint4 pbv = *(const uint4*)(g_p2b + i0);
    uint2 lv  = *(const uint2*)(g_lamh + i0);
    __half2 xw4 = g_xbar[(i0 & ~(long)511) | ((w+4)&511)];       // w+4 neighbor (wrap)
    const __half2* xb = (const __half2*)&xbv;
    const __half2* xh2 = (const __half2*)&xhv;
    __half2* pa = (__half2*)&pav;
    __half2* pb = (__half2*)&pbv;
    const __half* L4 = (const __half*)&lv;
    #pragma unroll
    for (int k = 0; k < 4; k++){
        float2 xbf = __half22float2(xb[k]);
        float2 xhf = __half22float2(xh2[k]);
        float2 xwf = __half22float2((k < 3) ? xb[k+1] : xw4);
        float  L   = __half2float(L4[k]);
        float2 paf = __half22float2(pa[k]);
        float2 pbf = __half22float2(pb[k]);
        float qax = paf.x + SIG*(xhf.x - xbf.x);
        float qay = paf.y + SIG*(xhf.y - xbf.y);
        float qbx = pbf.x + SIG*(xwf.x - xbf.x);
        float qby = pbf.y + SIG*(xwf.y - xbf.y);
        pa[k] = __floats2half2_rn(fminf(fmaxf(qax,-L),L), fminf(fmaxf(qay,-L),L));
        pb[k] = __floats2half2_rn(fminf(fmaxf(qbx,-L),L), fminf(fmaxf(qby,-L),L));
    }
    *(uint4*)(g_p2a + i0) = pav;
    *(uint4*)(g_p2b + i0) = pbv;
}

__global__ __launch_bounds__(128, 8) void k_fused(){
    extern __shared__ char smraw[];
    int bid = blockIdx.x;
    if (bid % 3 == 0){
        col_role(bid / 3, smraw);       // 4096 col blocks
    } else {
        p2_role4(bid - bid/3 - 1);      // 8192 p2 blocks
    }
}

// ---------------- C: row iFFT + primal update + forward row FFT of new xbar ----------------
// 128 threads = 2 FFT lines/block: 64-reg cap, narrow barriers, 8 contexts/SM.
__global__ __launch_bounds__(128, 8) void k_row(float2* __restrict__ x){
    __shared__ float2 sh_ex[2*EXSZ];
    int tid = threadIdx.x;
    int grp = tid >> 6, t = tid & 63;
    int row = blockIdx.x*2 + grp;          // row = b*512 + h
    int b = row >> 9, h = row & 511;
    float2* ex = sh_ex + grp*EXSZ;

    float2 r[8];
    {
        const uint4* src = (const uint4*)(g_T + ((long)row << 9) + (t<<3));
        uint4 tv0 = src[0], tv1 = src[1];
        const __half2* hp0 = (const __half2*)&tv0;
        const __half2* hp1 = (const __half2*)&tv1;
        #pragma unroll
        for (int j = 0; j < 4; j++) r[j]   = __half22float2(hp0[j]);
        #pragma unroll
        for (int j = 0; j < 4; j++) r[4+j] = __half22float2(hp1[j]);
    }
    fft512_line<false>(r, t, ex);          // reg a = v_raw at w = t+64a

    float sgn = ((h + t) & 1) ? -1.f : 1.f;
    float vc = sgn * SCL;

    long rbase = (long)row << 9;
    int hm = (h + 511) & 511;
    long rmbase = ((long)((b<<9) | hm)) << 9;

    #pragma unroll
    for (int a = 0; a < 8; a++){
        int w = t + (a<<6);
        int wm = (w + 511) & 511;
        float2 xo = x[rbase + w];
        float2 pam = __half22float2(g_p2a[rmbase + w]);
        float2 pac = __half22float2(g_p2a[rbase + w]);
        float2 pbm = __half22float2(g_p2b[rbase + wm]);
        float2 pbc = __half22float2(g_p2b[rbase + w]);
        float divx = (pam.x - pac.x) + (pbm.x - pbc.x);
        float divy = (pam.y - pac.y) + (pbm.y - pbc.y);
        float nx = xo.x - TAU*(vc*r[a].x + divx);
        float ny = xo.y - TAU*(vc*r[a].y + divy);
        x[rbase + w] = make_float2(nx, ny);
        float xbx = 2.f*nx - xo.x, xby = 2.f*ny - xo.y;
        g_xbar[rbase + w] = __floats2half2_rn(xbx, xby);
        r[a] = make_float2(sgn*xbx, sgn*xby);   // in-place: forward FFT input
    }

    fft512_line<true>(r, t, ex);
    {
        uint4 stg[2];
        __half2* sp = (__half2*)stg;
        #pragma unroll
        for (int j = 0; j < 8; j++) sp[j] = __floats2half2_rn(r[j].x*SCL, r[j].y*SCL);
        uint4* dst = (uint4*)(g_u1 + rbase + (t<<3));
        dst[0] = stg[0]; dst[1] = stg[1];
    }
}

// ---------------- launch ----------------
extern "C" void kernel_launch(void* const* d_in, const int* in_sizes, int n_in,
                              void* d_out, int out_size) {
    const float* ir  = (const float*)d_in[0];
    const float* ii  = (const float*)d_in[1];
    const float* kr  = (const float*)d_in[2];
    const float* ki  = (const float*)d_in[3];
    const float* lam = (const float*)d_in[4];
    const int*   msk = (const int*)  d_in[5];
    float2* x = (float2*)d_out;

    k_tw<<<1, 512>>>();
    k_init<<<NPIX/256, 256>>>(ir, ii, kr, ki, lam, msk, x);
    k_rowF<<<(NB*NH)/4, 256>>>();

    for (int it = 0; it < NIT; it++){
        k_fused<<<FUSEGRID, 128, COLSMEM>>>();
        k_row<<<(NB*NH)/2, 128>>>(x);
    }
}

// round 17
// speedup vs baseline: 1.1577x; 1.1577x over previous
#include <cuda_runtime.h>
#include <cuda_fp16.h>

#define NB 16
#define NH 512
#define NW 512
#define NPIX (NB*NH*NW)
#define NIT 128

// ---------------- device scratch (allocation-free), 16B-aligned ----------------
__device__ __align__(16) __half2 g_xbar[NPIX];  // fp16 transient: extrapolated primal (TV path only)
__device__ __align__(16) float2  g_P1[NPIX];    // dual p1 (fp32), S-conjugated, [b][pw][ph] digit-reversed
__device__ __align__(16) __half2 g_p2a[NPIX];   // fp16 TV dual, h-component (clamp re-anchors each iter)
__device__ __align__(16) __half2 g_p2b[NPIX];   // fp16 TV dual, w-component
__device__ __align__(16) __half2 g_u1[NPIX];    // fp16 transient: rowFFT(S*xbar), [b][h][pw]
__device__ __align__(16) __half2 g_T[NPIX];     // fp16 transient: col-iFFT(m*P1), [b][h][pw]
__device__ __align__(16) __half2 g_Y[NPIX];     // fp16: S*y, permuted to [b][pw][ph]
__device__ __align__(16) __half  g_lamh[NPIX];  // fp16 lambda
__device__ __align__(16) float   g_M[NH*NW];    // mask permuted to [pw][ph]
__device__ __align__(16) float2  g_tw[512];     // exp(-2*pi*i*j/512)

#define SIG    ((float)(0.97/3.0))
#define TAU    ((float)(0.97/3.0))
#define INV1PS ((float)(1.0/(1.0+0.97/3.0)))
#define SCL    (0.044194173824159223f)   // 1/sqrt(512)

// ---------------- complex helpers ----------------
__device__ __forceinline__ float2 cadd(float2 a, float2 b){ return make_float2(a.x+b.x, a.y+b.y); }
__device__ __forceinline__ float2 csub(float2 a, float2 b){ return make_float2(a.x-b.x, a.y-b.y); }
__device__ __forceinline__ float2 cmul(float2 a, float2 b){ return make_float2(a.x*b.x - a.y*b.y, a.x*b.y + a.y*b.x); }
__device__ __forceinline__ float2 cmulc(float2 a, float2 b){ return make_float2(a.x*b.x + a.y*b.y, a.y*b.x - a.x*b.y); } // a*conj(b)

template<int S>
__device__ __forceinline__ float2 rot90(float2 z){   // multiply by S*i
    return (S < 0) ? make_float2(z.y, -z.x) : make_float2(-z.y, z.x);
}

// 8-point DFT: X[k] = sum_n x[n] exp(S*2*pi*i*n*k/8), regs in place
template<int S>
__device__ __forceinline__ void dft8(float2 v[8]){
    const float sf = (float)S;
    float2 a0 = cadd(v[0], v[4]), a1 = csub(v[0], v[4]);
    float2 a2 = cadd(v[2], v[6]), a3 = csub(v[2], v[6]);
    float2 a4 = cadd(v[1], v[5]), a5 = csub(v[1], v[5]);
    float2 a6 = cadd(v[3], v[7]), a7 = csub(v[3], v[7]);
    float2 w3 = rot90<S>(a3);
    float2 w7 = rot90<S>(a7);
    float2 E0 = cadd(a0, a2), E2 = csub(a0, a2);
    float2 E1 = cadd(a1, w3), E3 = csub(a1, w3);
    float2 O0 = cadd(a4, a6), O2 = csub(a4, a6);
    float2 O1 = cadd(a5, w7), O3 = csub(a5, w7);
    const float r = 0.7071067811865476f;
    float2 t1 = make_float2(r*(O1.x - sf*O1.y), r*(O1.y + sf*O1.x));
    float2 t2 = rot90<S>(O2);
    float2 t3 = make_float2(r*(-O3.x - sf*O3.y), r*(-O3.y + sf*O3.x));
    v[0]=cadd(E0,O0); v[4]=csub(E0,O0);
    v[1]=cadd(E1,t1); v[5]=csub(E1,t1);
    v[2]=cadd(E2,t2); v[6]=csub(E2,t2);
    v[3]=cadd(E3,t3); v[7]=csub(E3,t3);
}

// 8x8 transpose among the 8 consecutive lanes sharing k0 (lanes m2=0..7 within group).
// new_r[j]@lane m2 = old_r[m2]@lane j — exactly the xB exchange permutation.
// Butterfly: 3 stages (m = 1,2,4); per stage, each (j0, j0|m) reg pair exchanges
// across lane pairs (lane, lane^m). Bit-identical to the smem version.
__device__ __forceinline__ void xpose8(float2 r[8], int m2){
    #pragma unroll
    for (int m = 1; m < 8; m <<= 1){
        bool hi = (m2 & m) != 0;
        #pragma unroll
        for (int j0 = 0; j0 < 8; j0++){
            if ((j0 & m) == 0){
                int j1 = j0 | m;
                float sx = hi ? r[j0].x : r[j1].x;
                float sy = hi ? r[j0].y : r[j1].y;
                float gx = __shfl_xor_sync(0xFFFFFFFFu, sx, m);
                float gy = __shfl_xor_sync(0xFFFFFFFFu, sy, m);
                if (hi){ r[j0].x = gx; r[j0].y = gy; }
                else   { r[j1].x = gx; r[j1].y = gy; }
            }
        }
    }
}

// xA exchange mapping (stride-64 blocks), conflict-free
__device__ __forceinline__ int xA(int i){ return i + ((i >> 6) << 3); }  // +8 pad per 64
#define EXSZ 576

// 512-pt FFT, 64 threads (t=0..63), 8 complex regs/thread. Unscaled.
// xA exchange is 64-thread-wide -> __syncthreads() smem exchange.
// xB exchange couples only the 8 consecutive lanes sharing k0 -> warp-shuffle
// 8x8 transpose (xpose8), no smem, no syncs.
// FWD:  in  r[a] = x[t+64a] (natural)      -> out r[j] = X at storage p = 8t+j (digit-reversed)
// !FWD: in  r[j] = data at storage p=8t+j  -> out r[a] = x[t+64a] (natural), sign +1 (times N)
template<bool FWD>
__device__ __forceinline__ void fft512_line(float2 r[8], int t, float2* ex){
    int k0 = t >> 3, m2 = t & 7;
    if (FWD){
        dft8<-1>(r);
        #pragma unroll
        for (int k = 1; k < 8; k++) r[k] = cmul(r[k], g_tw[t*k]);
        __syncthreads();
        #pragma unroll
        for (int k = 0; k < 8; k++) ex[xA((k<<6) + t)] = r[k];
        __syncthreads();
        #pragma unroll
        for (int m1 = 0; m1 < 8; m1++) r[m1] = ex[xA((k0<<6) + m2 + (m1<<3))];
        dft8<-1>(r);
        #pragma unroll
        for (int j = 1; j < 8; j++) r[j] = cmul(r[j], g_tw[(m2<<3)*j]);
        xpose8(r, m2);
        dft8<-1>(r);
    } else {
        dft8<1>(r);
        xpose8(r, m2);
        #pragma unroll
        for (int j = 1; j < 8; j++) r[j] = cmulc(r[j], g_tw[(m2<<3)*j]);
        dft8<1>(r);
        #pragma unroll
        for (int m1 = 0; m1 < 8; m1++) ex[xA((k0<<6) + m2 + (m1<<3))] = r[m1];
        __syncthreads();
        #pragma unroll
        for (int k = 0; k < 8; k++) r[k] = ex[xA((k<<6) + t)];
        #pragma unroll
        for (int k = 1; k < 8; k++) r[k] = cmulc(r[k], g_tw[t*k]);
        dft8<1>(r);
    }
}

__device__ __forceinline__ int rev8(int p){ return ((p & 7) << 6) | (p & 56) | (p >> 6); }

// ---------------- init kernels ----------------
__global__ void k_tw(){
    int j = threadIdx.x;
    double a = -6.283185307179586476925286766559 * (double)j / 512.0;
    g_tw[j] = make_float2((float)cos(a), (float)sin(a));
}

__global__ void k_init(const float* __restrict__ ir, const float* __restrict__ ii,
                       const float* __restrict__ kr, const float* __restrict__ ki,
                       const float* __restrict__ lam,
                       const int* __restrict__ mask, float2* __restrict__ xout){
    int i = blockIdx.x*256 + threadIdx.x;
    float2 x0 = make_float2(ir[i], ii[i]);
    xout[i] = x0;
    g_xbar[i] = __floats2half2_rn(x0.x, x0.y);
    __half2 hz = __floats2half2_rn(0.f, 0.f);
    g_P1[i] = make_float2(0.f, 0.f);
    g_p2a[i] = hz; g_p2b[i] = hz;
    g_lamh[i] = __float2half(lam[i]);
    // Y transposed+permuted: i = (b*512 + pw)*512 + ph
    int b = i >> 18, pw = (i >> 9) & 511, ph = i & 511;
    int kh = rev8(ph), kw = rev8(pw);
    float sg = ((kh + kw) & 1) ? -1.f : 1.f;
    int src = (b << 18) | (kh << 9) | kw;
    g_Y[i] = __floats2half2_rn(sg*kr[src], sg*ki[src]);
    if (i < NH*NW){
        int pw2 = i >> 9, ph2 = i & 511;
        g_M[i] = (float)mask[(rev8(ph2) << 9) | rev8(pw2)];
    }
}

// ---------------- bootstrap: U1 = rowFFT(S*xbar), fp16 in/out ----------------
__global__ __launch_bounds__(256) void k_rowF(){
    __shared__ float2 sh_ex[4*EXSZ];
    int tid = threadIdx.x;
    int grp = tid >> 6, t = tid & 63;
    int row = blockIdx.x*4 + grp;         // row = b*512 + h
    int h = row & 511;
    float2* ex = sh_ex + grp*EXSZ;
    float sgn = ((h + t) & 1) ? -1.f : 1.f;
    float2 r[8];
    const __half2* src = g_xbar + ((long)row << 9);
    #pragma unroll
    for (int a = 0; a < 8; a++){
        float2 v = __half22float2(src[t + (a<<6)]);
        r[a] = make_float2(sgn*v.x, sgn*v.y);
    }
    fft512_line<true>(r, t, ex);
    uint4 stg[2];
    __half2* sp = (__half2*)stg;
    #pragma unroll
    for (int j = 0; j < 8; j++) sp[j] = __floats2half2_rn(r[j].x*SCL, r[j].y*SCL);
    uint4* dst = (uint4*)(g_u1 + ((long)row << 9) + (t<<3));
    dst[0] = stg[0]; dst[1] = stg[1];
}

// ---------------- fused kernel: col-role (FFT) + p2-role (TV prox), grid-concatenated ----------------
#define CTILE 4
#define CPITCH 5
#define COLSMEM (4*EXSZ*sizeof(float2))       // 18432 B; half2 tile (10240 B) overlays exchange
#define COLBLKS (NB*128)                      // 2048
#define P2BLKS  (NPIX/1024)                   // 4096  (4 px/thread, 256 thr)
#define FUSEGRID (COLBLKS + P2BLKS)           // 6144, interleave 1:2 (bid%3)

__device__ __forceinline__ void col_role(int cb, char* smraw){
    __half2* tile = (__half2*)smraw;           // 512 x CPITCH half2 (10240 B)
    float2*  exb  = (float2*)smraw;            // overlays tile
    int tid = threadIdx.x;
    int b  = cb >> 7;
    int w0 = (cb & 127) * CTILE;
    int g  = tid >> 6, t = tid & 63;
    float2* ex = exb + g*EXSZ;

    // load U1 tile: thread tid loads rows tid and tid+256 (CTILE half2 = 16B = 1 uint4)
    #pragma unroll
    for (int rr = 0; rr < 2; rr++){
        int hh = tid + (rr<<8);
        uint4 v = *(const uint4*)(g_u1 + (((long)(b<<9) + hh) << 9) + w0);
        const __half2* hv = (const __half2*)&v;
        __half2* dst = tile + hh*CPITCH;
        dst[0] = hv[0]; dst[1] = hv[1]; dst[2] = hv[2]; dst[3] = hv[3];
    }
    __syncthreads();

    // gather column pw = w0+g into regs (reg a = element h = t+64a); stride 5 words -> conflict-free
    float2 r[8];
    #pragma unroll
    for (int a = 0; a < 8; a++) r[a] = __half22float2(tile[(t + (a<<6))*CPITCH + g]);
    // tile dead; FWD fft's pre-write __syncthreads fences the aliased exchange writes

    fft512_line<true>(r, t, ex);   // reg j = u at ph = 8t+j (unscaled)

    // pointwise: P1 prox + mask — short live ranges; Y fp16
    {
        int pw = w0 + g;
        long base = (((long)(b<<9) + pw) << 9) + (t<<3);
        const float4* p1p = (const float4*)(g_P1 + base);
        const uint4*  yp  = (const uint4*)(g_Y  + base);   // 8 half2 = 2 uint4
        const float4* mp  = (const float4*)(g_M + ((long)pw << 9) + (t<<3));
        float4* p1o = (float4*)(g_P1 + base);
        uint4 yv[2] = {yp[0], yp[1]};
        const __half2* yh = (const __half2*)yv;
        float4 mv0 = mp[0], mv1 = mp[1];
        const float* m8a = (const float*)&mv0;
        const float* m8b = (const float*)&mv1;
        #pragma unroll
        for (int q = 0; q < 4; q++){
            float4 p1v = p1p[q];
            float m0 = (q < 2) ? m8a[2*q]   : m8b[2*q-4];
            float m1 = (q < 2) ? m8a[2*q+1] : m8b[2*q-3];
            int j = 2*q;
            float2 yy0 = __half22float2(yh[j]);
            float2 yy1 = __half22float2(yh[j+1]);
            float nx0 = (p1v.x + SIG*(m0*(r[j].x*SCL))   - SIG*yy0.x) * INV1PS;
            float ny0 = (p1v.y + SIG*(m0*(r[j].y*SCL))   - SIG*yy0.y) * INV1PS;
            float nx1 = (p1v.z + SIG*(m1*(r[j+1].x*SCL)) - SIG*yy1.x) * INV1PS;
            float ny1 = (p1v.w + SIG*(m1*(r[j+1].y*SCL)) - SIG*yy1.y) * INV1PS;
            p1o[q] = make_float4(nx0, ny0, nx1, ny1);
            r[j]   = make_float2(m0*nx0, m0*ny0);
            r[j+1] = make_float2(m1*nx1, m1*ny1);
        }
    }

    fft512_line<false>(r, t, ex);  // reg a = element h = t+64a (unscaled)

    __syncthreads();               // all exchange reads done before tile re-staging (overlay)
    #pragma unroll
    for (int a = 0; a < 8; a++)
        tile[(t + (a<<6))*CPITCH + g] = __floats2half2_rn(r[a].x*SCL, r[a].y*SCL);
    __syncthreads();
    #pragma unroll
    for (int rr = 0; rr < 2; rr++){
        int hh = tid + (rr<<8);
        const __half2* s2 = tile + hh*CPITCH;
        uint4 v;
        __half2* hv = (__half2*)&v;
        hv[0] = s2[0]; hv[1] = s2[1]; hv[2] = s2[2]; hv[3] = s2[3];
        *(uint4*)(g_T + (((long)(b<<9) + hh) << 9) + w0) = v;
    }
}

// p2-role: 4 consecutive px/thread, uint4-vectorized (i0 16B-aligned)
__device__ __forceinline__ void p2_role4(int pid){
    int tid = threadIdx.x;
    long i0 = (long)pid*1024 + tid*4;
    int w = (int)(i0 & 511);
    int h = (int)((i0 >> 9) & 511);
    long ih = (i0 & ~((long)511<<9)) | ((long)((h+1)&511)<<9);   // same b,w; row h+1
    uint4 xbv = *(const uint4*)(g_xbar + i0);
    uint4 xhv = *(const uint4*)(g_xbar + ih);
    uint4 pav = *(const uint4*)(g_p2a + i0);
    uint4 pbv = *(const uint4*)(g_p2b + i0);
    uint2 lv  = *(const uint2*)(g_lamh + i0);
    __half2 xw4 = g_xbar[(i0 & ~(long)511) | ((w+4)&511)];       // w+4 neighbor (wrap)
    const __half2* xb = (const __half2*)&xbv;
    const __half2* xh2 = (const __half2*)&xhv;
    __half2* pa = (__half2*)&pav;
    __half2* pb = (__half2*)&pbv;
    const __half* L4 = (const __half*)&lv;
    #pragma unroll
    for (int k = 0; k < 4; k++){
        float2 xbf = __half22float2(xb[k]);
        float2 xhf = __half22float2(xh2[k]);
        float2 xwf = __half22float2((k < 3) ? xb[k+1] : xw4);
        float  L   = __half2float(L4[k]);
        float2 paf = __half22float2(pa[k]);
        float2 pbf = __half22float2(pb[k]);
        float qax = paf.x + SIG*(xhf.x - xbf.x);
        float qay = paf.y + SIG*(xhf.y - xbf.y);
        float qbx = pbf.x + SIG*(xwf.x - xbf.x);
        float qby = pbf.y + SIG*(xwf.y - xbf.y);
        pa[k] = __floats2half2_rn(fminf(fmaxf(qax,-L),L), fminf(fmaxf(qay,-L),L));
        pb[k] = __floats2half2_rn(fminf(fmaxf(qbx,-L),L), fminf(fmaxf(qby,-L),L));
    }
    *(uint4*)(g_p2a + i0) = pav;
    *(uint4*)(g_p2b + i0) = pbv;
}

__global__ __launch_bounds__(256, 4) void k_fused(){
    extern __shared__ char smraw[];
    int bid = blockIdx.x;
    if (bid % 3 == 0){
        col_role(bid / 3, smraw);       // 2048 col blocks
    } else {
        p2_role4(bid - bid/3 - 1);      // 4096 p2 blocks
    }
}

// ---------------- C: row iFFT + primal update + forward row FFT of new xbar ----------------
// 128 threads = 2 FFT lines/block: 64-reg cap, narrow barriers, 8 contexts/SM.
__global__ __launch_bounds__(128, 8) void k_row(float2* __restrict__ x){
    __shared__ float2 sh_ex[2*EXSZ];
    int tid = threadIdx.x;
    int grp = tid >> 6, t = tid & 63;
    int row = blockIdx.x*2 + grp;          // row = b*512 + h
    int b = row >> 9, h = row & 511;
    float2* ex = sh_ex + grp*EXSZ;

    float2 r[8];
    {
        const uint4* src = (const uint4*)(g_T + ((long)row << 9) + (t<<3));
        uint4 tv0 = src[0], tv1 = src[1];
        const __half2* hp0 = (const __half2*)&tv0;
        const __half2* hp1 = (const __half2*)&tv1;
        #pragma unroll
        for (int j = 0; j < 4; j++) r[j]   = __half22float2(hp0[j]);
        #pragma unroll
        for (int j = 0; j < 4; j++) r[4+j] = __half22float2(hp1[j]);
    }
    fft512_line<false>(r, t, ex);          // reg a = v_raw at w = t+64a

    float sgn = ((h + t) & 1) ? -1.f : 1.f;
    float vc = sgn * SCL;

    long rbase = (long)row << 9;
    int hm = (h + 511) & 511;
    long rmbase = ((long)((b<<9) | hm)) << 9;

    #pragma unroll
    for (int a = 0; a < 8; a++){
        int w = t + (a<<6);
        int wm = (w + 511) & 511;
        float2 xo = x[rbase + w];
        float2 pam = __half22float2(g_p2a[rmbase + w]);
        float2 pac = __half22float2(g_p2a[rbase + w]);
        float2 pbm = __half22float2(g_p2b[rbase + wm]);
        float2 pbc = __half22float2(g_p2b[rbase + w]);
        float divx = (pam.x - pac.x) + (pbm.x - pbc.x);
        float divy = (pam.y - pac.y) + (pbm.y - pbc.y);
        float nx = xo.x - TAU*(vc*r[a].x + divx);
        float ny = xo.y - TAU*(vc*r[a].y + divy);
        x[rbase + w] = make_float2(nx, ny);
        float xbx = 2.f*nx - xo.x, xby = 2.f*ny - xo.y;
        g_xbar[rbase + w] = __floats2half2_rn(xbx, xby);
        r[a] = make_float2(sgn*xbx, sgn*xby);   // in-place: forward FFT input
    }

    fft512_line<true>(r, t, ex);
    {
        uint4 stg[2];
        __half2* sp = (__half2*)stg;
        #pragma unroll
        for (int j = 0; j < 8; j++) sp[j] = __floats2half2_rn(r[j].x*SCL, r[j].y*SCL);
        uint4* dst = (uint4*)(g_u1 + rbase + (t<<3));
        dst[0] = stg[0]; dst[1] = stg[1];
    }
}

// ---------------- launch ----------------
extern "C" void kernel_launch(void* const* d_in, const int* in_sizes, int n_in,
                              void* d_out, int out_size) {
    const float* ir  = (const float*)d_in[0];
    const float* ii  = (const float*)d_in[1];
    const float* kr  = (const float*)d_in[2];
    const float* ki  = (const float*)d_in[3];
    const float* lam = (const float*)d_in[4];
    const int*   msk = (const int*)  d_in[5];
    float2* x = (float2*)d_out;

    k_tw<<<1, 512>>>();
    k_init<<<NPIX/256, 256>>>(ir, ii, kr, ki, lam, msk, x);
    k_rowF<<<(NB*NH)/4, 256>>>();

    for (int it = 0; it < NIT; it++){
        k_fused<<<FUSEGRID, 256, COLSMEM>>>();
        k_row<<<(NB*NH)/2, 128>>>(x);
    }
}